// round 13
// baseline (speedup 1.0000x reference)
#include <cuda_runtime.h>
#include <math.h>
#include <stdint.h>

// Problem constants
#define B_   1024
#define L_   50
#define H_   256
#define N_   100000
#define A_   100
#define NN_  99999
#define BL_  (B_ * L_)   // 51200
#define QKN  200

// Scratch (device globals — no runtime allocation allowed)
__device__ float g_final_rep[B_ * H_];            // 1 MB (tf32 bits)
__device__ float g_qk[(size_t)BL_ * QKN];         // 41 MB
__device__ float g_cat[B_ * 2 * H_];              // 2 MB
__device__ float g_embt[(size_t)N_ * H_];         // 102 MB (tf32 bits)
__device__ float g_wt[QKN * H_];                  // 200 KB (tf32 [Qw;Kw])

// ---------------------------------------------------------------------------
// helpers
// ---------------------------------------------------------------------------
__device__ __forceinline__ uint32_t f2tf32(float f) {
    uint32_t r;
    asm("cvt.rna.tf32.f32 %0, %1;" : "=r"(r) : "f"(f));
    return r;
}
__device__ __forceinline__ void mma_tf32(float* c, const uint32_t* a,
                                         const uint32_t* b) {
    asm volatile(
        "mma.sync.aligned.m16n8k8.row.col.f32.tf32.tf32.f32 "
        "{%0,%1,%2,%3}, {%4,%5,%6,%7}, {%8,%9}, {%0,%1,%2,%3};"
        : "+f"(c[0]), "+f"(c[1]), "+f"(c[2]), "+f"(c[3])
        : "r"(a[0]), "r"(a[1]), "r"(a[2]), "r"(a[3]),
          "r"(b[0]), "r"(b[1]));
}
__device__ __forceinline__ uint32_t smem_u32(const void* p) {
    uint32_t a;
    asm("{ .reg .u64 t; cvta.to.shared.u64 t, %1; cvt.u32.u64 %0, t; }"
        : "=r"(a) : "l"(p));
    return a;
}
__device__ __forceinline__ void cpasync16(uint32_t dst, const void* src) {
    asm volatile("cp.async.cg.shared.global [%0], [%1], 16;"
                 :: "r"(dst), "l"(src));
}
__device__ __forceinline__ void cp_commit() {
    asm volatile("cp.async.commit_group;" ::: "memory");
}

#define BM  128
#define BN  128
#define BK  32
#define BKP 36
#define GEMM_SMEM (2 * (BM + BN) * BKP * 4)        // 73728
#define K1A_SMEM  (GEMM_SMEM + 512)

// ---------------------------------------------------------------------------
// k0: emb -> g_embt (tf32 bits);  k0b: [Qw;Kw] -> g_wt
// ---------------------------------------------------------------------------
__global__ void __launch_bounds__(256) k0_cvt(const float* __restrict__ emb)
{
    size_t i = (size_t)blockIdx.x * 256 + threadIdx.x;
    float4 v = ((const float4*)emb)[i];
    ((uint4*)g_embt)[i] = make_uint4(f2tf32(v.x), f2tf32(v.y),
                                     f2tf32(v.z), f2tf32(v.w));
}
__global__ void __launch_bounds__(256) k0b_cvt(const float* __restrict__ Qw,
                                               const float* __restrict__ Kw)
{
    int i = blockIdx.x * 256 + threadIdx.x;        // float4 idx, 12800 total
    int half = (A_ * H_) / 4;                      // 6400
    float4 v = (i < half) ? ((const float4*)Qw)[i]
                          : ((const float4*)Kw)[i - half];
    ((uint4*)g_wt)[i] = make_uint4(f2tf32(v.x), f2tf32(v.y),
                                   f2tf32(v.z), f2tf32(v.w));
}

// ---------------------------------------------------------------------------
// k1a: QK = sigmoid( X @ [Qw;Kw]^T ), cp.async version
//   A rows gathered from g_embt via inputs; B = g_wt. 256 thr, 2 CTA/SM.
// ---------------------------------------------------------------------------
__global__ void __launch_bounds__(256, 2) k1a_mma(const int* __restrict__ inputs)
{
    extern __shared__ float sm2[];
    float* Abuf = sm2;
    float* Bbuf = sm2 + 2 * BM * BKP;
    int*   s_ids = (int*)(sm2 + 2 * (BM + BN) * BKP);
    const uint32_t sA = smem_u32(Abuf);
    const uint32_t sB = smem_u32(Bbuf);

    const int tid  = threadIdx.x;
    const int lane = tid & 31;
    const int wid  = tid >> 5;
    const int l4   = lane & 3;
    const int lq   = lane >> 2;
    const int wm   = (wid & 1) * 64;
    const int wn   = (wid >> 1) * 32;

    const int m0 = blockIdx.x * BM;
    const int n0 = blockIdx.y * BN;

    if (tid < 128) s_ids[tid] = inputs[m0 + tid];
    __syncthreads();

    float c[4][4][4];
#pragma unroll
    for (int mi = 0; mi < 4; mi++)
#pragma unroll
        for (int ni = 0; ni < 4; ni++)
#pragma unroll
            for (int j = 0; j < 4; j++) c[mi][ni][j] = 0.f;

    int rowi[4], qi[4];
    const float* asrc[4];
    const float* bsrc[4];
#pragma unroll
    for (int i = 0; i < 4; i++) {
        int v = tid + i * 256;
        rowi[i] = v >> 3;
        qi[i]   = (v & 7) * 4;
        asrc[i] = g_embt + (size_t)s_ids[rowi[i]] * H_ + qi[i];
        int gb = n0 + rowi[i]; if (gb > QKN - 1) gb = QKN - 1;
        bsrc[i] = g_wt + (size_t)gb * H_ + qi[i];
    }

#pragma unroll
    for (int s = 0; s < 2; s++) {
        const uint32_t ab = sA + (uint32_t)s * BM * BKP * 4;
        const uint32_t bb = sB + (uint32_t)s * BN * BKP * 4;
        const int ko = s * BK;
#pragma unroll
        for (int i = 0; i < 4; i++) {
            cpasync16(ab + (uint32_t)(rowi[i] * BKP + qi[i]) * 4, asrc[i] + ko);
            cpasync16(bb + (uint32_t)(rowi[i] * BKP + qi[i]) * 4, bsrc[i] + ko);
        }
        cp_commit();
    }

#pragma unroll 1
    for (int s = 0; s < H_ / BK; s++) {
        const int buf = s & 1;
        if (s < H_ / BK - 1)
            asm volatile("cp.async.wait_group 1;" ::: "memory");
        else
            asm volatile("cp.async.wait_group 0;" ::: "memory");
        __syncthreads();

        const uint32_t* Au = (const uint32_t*)(Abuf + buf * BM * BKP);
        const uint32_t* Bu = (const uint32_t*)(Bbuf + buf * BN * BKP);
#pragma unroll
        for (int kk = 0; kk < 4; kk++) {
            const int kb = kk * 8;
            uint32_t a[4][4], bfr[4][2];
#pragma unroll
            for (int mi = 0; mi < 4; mi++) {
                int r = wm + mi * 16 + lq;
                a[mi][0] = Au[(r)     * BKP + kb + l4];
                a[mi][1] = Au[(r + 8) * BKP + kb + l4];
                a[mi][2] = Au[(r)     * BKP + kb + l4 + 4];
                a[mi][3] = Au[(r + 8) * BKP + kb + l4 + 4];
            }
#pragma unroll
            for (int ni = 0; ni < 4; ni++) {
                int n = wn + ni * 8 + lq;
                bfr[ni][0] = Bu[n * BKP + kb + l4];
                bfr[ni][1] = Bu[n * BKP + kb + l4 + 4];
            }
#pragma unroll
            for (int mi = 0; mi < 4; mi++)
#pragma unroll
                for (int ni = 0; ni < 4; ni++)
                    mma_tf32(c[mi][ni], a[mi], bfr[ni]);
        }
        __syncthreads();

        if (s + 2 < H_ / BK) {
            const uint32_t ab = sA + (uint32_t)buf * BM * BKP * 4;
            const uint32_t bb = sB + (uint32_t)buf * BN * BKP * 4;
            const int ko = (s + 2) * BK;
#pragma unroll
            for (int i = 0; i < 4; i++) {
                cpasync16(ab + (uint32_t)(rowi[i] * BKP + qi[i]) * 4, asrc[i] + ko);
                cpasync16(bb + (uint32_t)(rowi[i] * BKP + qi[i]) * 4, bsrc[i] + ko);
            }
            cp_commit();
        }
    }

    float* so = sm2;   // [128][129]
#pragma unroll
    for (int mi = 0; mi < 4; mi++) {
        int r = wm + mi * 16 + lq;
#pragma unroll
        for (int ni = 0; ni < 4; ni++) {
            int cn = wn + ni * 8 + 2 * l4;
            so[(r)     * 129 + cn]     = c[mi][ni][0];
            so[(r)     * 129 + cn + 1] = c[mi][ni][1];
            so[(r + 8) * 129 + cn]     = c[mi][ni][2];
            so[(r + 8) * 129 + cn + 1] = c[mi][ni][3];
        }
    }
    __syncthreads();

#pragma unroll 8
    for (int i = tid; i < BM * BN; i += 256) {
        int r = i >> 7, cn = i & 127;
        int col = n0 + cn;
        if (col < QKN)
            g_qk[(size_t)(m0 + r) * QKN + col] =
                1.f / (1.f + expf(-so[r * 129 + cn]));
    }
}

// ---------------------------------------------------------------------------
// k1b: per-batch affinity + softmax + att -> g_cat (unchanged)
// ---------------------------------------------------------------------------
__global__ void __launch_bounds__(256) k1b_kernel(
    const int*   __restrict__ inputs,
    const float* __restrict__ masks,
    const float* __restrict__ emb,
    float*       __restrict__ out_aff)
{
    extern __shared__ float sm[];
    float* s_Q     = sm;
    float* s_K     = s_Q + L_ * A_;
    float* s_aff   = s_K + L_ * A_;
    float* s_score = s_aff + L_ * L_;
    float* s_mask  = s_score + 64;
    int*   s_idx   = (int*)(s_mask + 64);
    int*   s_misc  = s_idx + 64;

    const int b   = blockIdx.x;
    const int tid = threadIdx.x;

    if (tid < L_) {
        s_idx[tid]  = inputs[b * L_ + tid];
        s_mask[tid] = masks[b * L_ + tid];
    }

    const float4* qrow = (const float4*)(g_qk + (size_t)b * L_ * QKN);
    for (int v = tid; v < L_ * (QKN / 4); v += 256) {
        int l = v / (QKN / 4);
        int j = v - l * (QKN / 4);
        float4 t = qrow[v];
        if (j < A_ / 4) ((float4*)(s_Q + l * A_))[j] = t;
        else            ((float4*)(s_K + l * A_))[j - A_ / 4] = t;
    }
    __syncthreads();

    for (int p = tid; p < L_ * L_; p += 256) {
        int l = p / L_;
        int m = p - l * L_;
        const float4* qr = (const float4*)(s_Q + l * A_);
        const float4* kr = (const float4*)(s_K + m * A_);
        float acc = 0.f;
#pragma unroll
        for (int c = 0; c < A_ / 4; c++) {
            float4 q4 = qr[c], k4 = kr[c];
            acc += q4.x * k4.x + q4.y * k4.y + q4.z * k4.z + q4.w * k4.w;
        }
        acc *= 0.1f;
        s_aff[p] = acc;
        out_aff[(size_t)b * (L_ * L_) + p] = acc;
    }
    __syncthreads();

    if (tid < L_) {
        float s = 0.f;
        for (int m = 0; m < L_; m++) s += s_aff[tid * L_ + m] * s_mask[m];
        s -= s_aff[tid * L_ + tid] * s_mask[tid];
        s_score[tid] = s * s_mask[tid];
    }
    __syncthreads();

    if (tid == 0) {
        float mx = -1e30f;
        for (int l = 0; l < L_; l++) mx = fmaxf(mx, s_score[l]);
        float sum = 0.f;
        for (int l = 0; l < L_; l++) {
            float e = expf(s_score[l] - mx) * s_mask[l];
            s_aff[l] = e;
            sum += e;
        }
        float inv = 1.f / sum;
        for (int l = 0; l < L_; l++) s_score[l] = s_aff[l] * inv;
        float fl = 0.f;
        for (int m = 0; m < L_; m++) fl += s_mask[m];
        s_misc[0] = s_idx[(int)fl - 1];
    }
    __syncthreads();

    const int last_id = s_misc[0];
    float lastv = emb[(size_t)last_id * H_ + tid];
    float att = 0.f;
#pragma unroll 10
    for (int l = 0; l < L_; l++)
        att += s_score[l] * emb[(size_t)s_idx[l] * H_ + tid];

    g_cat[(size_t)b * (2 * H_) + tid]      = att;
    g_cat[(size_t)b * (2 * H_) + H_ + tid] = lastv;
}

// ---------------------------------------------------------------------------
// k1c: final_rep = cat @ lin_w^T + lin_b (fp32; 4 batches/CTA, grid 256)
// ---------------------------------------------------------------------------
__global__ void __launch_bounds__(256) k1c_kernel(
    const float* __restrict__ lin_w,
    const float* __restrict__ lin_b)
{
    __shared__ float s_cat[4 * 2 * H_];    // 8 KB
    const int b0  = blockIdx.x * 4;
    const int tid = threadIdx.x;

    for (int v = tid; v < 4 * (2 * H_ / 4); v += 256)
        ((float4*)s_cat)[v] = ((const float4*)(g_cat + (size_t)b0 * 2 * H_))[v];
    __syncthreads();

    const float bias = lin_b[tid];
    float acc[4];
#pragma unroll
    for (int bb = 0; bb < 4; bb++) acc[bb] = bias;

    const float4* wrow = (const float4*)(lin_w + (size_t)tid * (2 * H_));
#pragma unroll 4
    for (int kc = 0; kc < 2 * H_ / 4; kc += 4) {
        float4 w0 = wrow[kc], w1 = wrow[kc + 1], w2 = wrow[kc + 2], w3 = wrow[kc + 3];
#pragma unroll
        for (int bb = 0; bb < 4; bb++) {
            const float4* cr = (const float4*)(s_cat + bb * 2 * H_) + kc;
            float4 c0 = cr[0], c1 = cr[1], c2 = cr[2], c3 = cr[3];
            acc[bb] += w0.x * c0.x + w0.y * c0.y + w0.z * c0.z + w0.w * c0.w
                     + w1.x * c1.x + w1.y * c1.y + w1.z * c1.z + w1.w * c1.w
                     + w2.x * c2.x + w2.y * c2.y + w2.z * c2.z + w2.w * c2.w
                     + w3.x * c3.x + w3.y * c3.y + w3.z * c3.z + w3.w * c3.w;
        }
    }
#pragma unroll
    for (int bb = 0; bb < 4; bb++)
        g_final_rep[(size_t)(b0 + bb) * H_ + tid] =
            __uint_as_float(f2tf32(acc[bb]));
}

// ---------------------------------------------------------------------------
// k2: scores = final_rep @ embt[1:]^T.  128 threads, 4 warps, 64x64 warp
//     tiles (LDS:MMA ratio 1.0), cp.async 2-stage, 2 CTA/SM.
// ---------------------------------------------------------------------------
__global__ void __launch_bounds__(128, 2) k2_mma(float* __restrict__ out)
{
    extern __shared__ float sm2[];
    float* Abuf = sm2;                      // [2][BM][BKP]
    float* Bbuf = sm2 + 2 * BM * BKP;       // [2][BN][BKP]
    const uint32_t sA = smem_u32(Abuf);
    const uint32_t sB = smem_u32(Bbuf);

    const int tid  = threadIdx.x;
    const int lane = tid & 31;
    const int wid  = tid >> 5;              // 0..3
    const int l4   = lane & 3;
    const int lq   = lane >> 2;
    const int wm   = (wid & 1) * 64;
    const int wn   = (wid >> 1) * 64;

    const int m0 = blockIdx.x * BM;
    const int n0 = blockIdx.y * BN;

    float c[4][8][4];
#pragma unroll
    for (int mi = 0; mi < 4; mi++)
#pragma unroll
        for (int ni = 0; ni < 8; ni++)
#pragma unroll
            for (int j = 0; j < 4; j++) c[mi][ni][j] = 0.f;

    const float* Ag = g_final_rep + (size_t)m0 * H_;

    int rowi[8], qi[8], gni[8];
#pragma unroll
    for (int i = 0; i < 8; i++) {
        int v = tid + i * 128;
        rowi[i] = v >> 3;
        qi[i]   = (v & 7) * 4;
        int gn = n0 + rowi[i] + 1; if (gn > N_ - 1) gn = N_ - 1;
        gni[i] = gn;
    }

#pragma unroll
    for (int s = 0; s < 2; s++) {
        const uint32_t ab = sA + (uint32_t)s * BM * BKP * 4;
        const uint32_t bb = sB + (uint32_t)s * BN * BKP * 4;
        const int ko = s * BK;
#pragma unroll
        for (int i = 0; i < 8; i++) {
            cpasync16(ab + (uint32_t)(rowi[i] * BKP + qi[i]) * 4,
                      Ag + (size_t)rowi[i] * H_ + ko + qi[i]);
            cpasync16(bb + (uint32_t)(rowi[i] * BKP + qi[i]) * 4,
                      g_embt + (size_t)gni[i] * H_ + ko + qi[i]);
        }
        cp_commit();
    }

#pragma unroll 1
    for (int s = 0; s < H_ / BK; s++) {
        const int buf = s & 1;
        if (s < H_ / BK - 1)
            asm volatile("cp.async.wait_group 1;" ::: "memory");
        else
            asm volatile("cp.async.wait_group 0;" ::: "memory");
        __syncthreads();

        const uint32_t* Au = (const uint32_t*)(Abuf + buf * BM * BKP);
        const uint32_t* Bu = (const uint32_t*)(Bbuf + buf * BN * BKP);
#pragma unroll
        for (int kk = 0; kk < 4; kk++) {
            const int kb = kk * 8;
            uint32_t a[4][4], bfr[8][2];
#pragma unroll
            for (int mi = 0; mi < 4; mi++) {
                int r = wm + mi * 16 + lq;
                a[mi][0] = Au[(r)     * BKP + kb + l4];
                a[mi][1] = Au[(r + 8) * BKP + kb + l4];
                a[mi][2] = Au[(r)     * BKP + kb + l4 + 4];
                a[mi][3] = Au[(r + 8) * BKP + kb + l4 + 4];
            }
#pragma unroll
            for (int ni = 0; ni < 8; ni++) {
                int n = wn + ni * 8 + lq;
                bfr[ni][0] = Bu[n * BKP + kb + l4];
                bfr[ni][1] = Bu[n * BKP + kb + l4 + 4];
            }
#pragma unroll
            for (int mi = 0; mi < 4; mi++)
#pragma unroll
                for (int ni = 0; ni < 8; ni++)
                    mma_tf32(c[mi][ni], a[mi], bfr[ni]);
        }
        __syncthreads();

        if (s + 2 < H_ / BK) {
            const uint32_t ab = sA + (uint32_t)buf * BM * BKP * 4;
            const uint32_t bb = sB + (uint32_t)buf * BN * BKP * 4;
            const int ko = (s + 2) * BK;
#pragma unroll
            for (int i = 0; i < 8; i++) {
                cpasync16(ab + (uint32_t)(rowi[i] * BKP + qi[i]) * 4,
                          Ag + (size_t)rowi[i] * H_ + ko + qi[i]);
                cpasync16(bb + (uint32_t)(rowi[i] * BKP + qi[i]) * 4,
                          g_embt + (size_t)gni[i] * H_ + ko + qi[i]);
            }
            cp_commit();
        }
    }

    // epilogue: fragments -> padded smem -> coalesced stores
    float* so = sm2;   // [128][129]
#pragma unroll
    for (int mi = 0; mi < 4; mi++) {
        int r = wm + mi * 16 + lq;
#pragma unroll
        for (int ni = 0; ni < 8; ni++) {
            int cn = wn + ni * 8 + 2 * l4;
            so[(r)     * 129 + cn]     = c[mi][ni][0];
            so[(r)     * 129 + cn + 1] = c[mi][ni][1];
            so[(r + 8) * 129 + cn]     = c[mi][ni][2];
            so[(r + 8) * 129 + cn + 1] = c[mi][ni][3];
        }
    }
    __syncthreads();

#pragma unroll 8
    for (int i = tid; i < BM * BN; i += 128) {
        int r = i >> 7, cn = i & 127;
        if (n0 + cn < NN_)
            out[(size_t)(m0 + r) * NN_ + n0 + cn] = so[r * 129 + cn];
    }
}

// ---------------------------------------------------------------------------
extern "C" void kernel_launch(void* const* d_in, const int* in_sizes, int n_in,
                              void* d_out, int out_size)
{
    const int*   inputs = (const int*)  d_in[0];
    const float* masks  = (const float*)d_in[1];
    const float* emb    = (const float*)d_in[2];
    const float* Qw     = (const float*)d_in[3];
    const float* Kw     = (const float*)d_in[4];
    const float* lin_w  = (const float*)d_in[5];
    const float* lin_b  = (const float*)d_in[6];

    float* out        = (float*)d_out;
    float* out_scores = out;
    float* out_aff    = out + (size_t)B_ * NN_;

    k0_cvt<<<(N_ * H_ / 4) / 256, 256>>>(emb);
    k0b_cvt<<<(QKN * H_ / 4 + 255) / 256, 256>>>(Qw, Kw);

    cudaFuncSetAttribute(k1a_mma,
                         cudaFuncAttributeMaxDynamicSharedMemorySize, K1A_SMEM);
    dim3 g1a(BL_ / BM, (QKN + BN - 1) / BN);
    k1a_mma<<<g1a, 256, K1A_SMEM>>>(inputs);

    const int smem1b = (L_*A_*2 + L_*L_ + 64 + 64 + 64 + 16) * 4;
    cudaFuncSetAttribute(k1b_kernel,
                         cudaFuncAttributeMaxDynamicSharedMemorySize, smem1b);
    k1b_kernel<<<B_, 256, smem1b>>>(inputs, masks, emb, out_aff);

    k1c_kernel<<<B_ / 4, 256>>>(lin_w, lin_b);

    cudaFuncSetAttribute(k2_mma,
                         cudaFuncAttributeMaxDynamicSharedMemorySize, GEMM_SMEM);
    dim3 g2(B_ / BM, (NN_ + BN - 1) / BN);
    k2_mma<<<g2, 128, GEMM_SMEM>>>(out_scores);

    (void)in_sizes; (void)n_in; (void)out_size;
}